// round 14
// baseline (speedup 1.0000x reference)
#include <cuda_runtime.h>
#include <cuda_bf16.h>
#include <cstdint>

// Problem constants: B=8, N=2048, D=DQ=DV=1024
#define BATCH 8
#define SEQ   2048
#define DIM   1024
#define ROWS  (BATCH * SEQ)        // 16384

// ---------------------------------------------------------------------------
// Device scratch
// ---------------------------------------------------------------------------
__device__ __nv_bfloat16 g_xhi[(size_t)ROWS * DIM];
__device__ __nv_bfloat16 g_xlo[(size_t)ROWS * DIM];
__device__ __nv_bfloat16 g_Wqthi[(size_t)DIM * DIM], g_Wqtlo[(size_t)DIM * DIM];
__device__ __nv_bfloat16 g_Wkthi[(size_t)DIM * DIM], g_Wktlo[(size_t)DIM * DIM];
__device__ __nv_bfloat16 g_Wvthi[(size_t)DIM * DIM], g_Wvtlo[(size_t)DIM * DIM];
__device__ __nv_bfloat16 g_Qhi[(size_t)ROWS * DIM], g_Qlo[(size_t)ROWS * DIM];
__device__ __nv_bfloat16 g_Khi[(size_t)ROWS * DIM], g_Klo[(size_t)ROWS * DIM];
__device__ __nv_bfloat16 g_Vthi[(size_t)BATCH * DIM * SEQ], g_Vtlo[(size_t)BATCH * DIM * SEQ];
__device__ __nv_bfloat16 g_Phi[(size_t)BATCH * SEQ * SEQ], g_Plo[(size_t)BATCH * SEQ * SEQ];
__device__ float g_rowsum[(size_t)ROWS];

// ---------------------------------------------------------------------------
// PTX helpers (portable sm_80+: mma.sync / ldmatrix / cp.async / mbarrier)
// ---------------------------------------------------------------------------
__device__ __forceinline__ uint32_t smem_to_u32(const void* p) {
    uint32_t a;
    asm("{ .reg .u64 t; cvta.to.shared.u64 t, %1; cvt.u32.u64 %0, t; }" : "=r"(a) : "l"(p));
    return a;
}
__device__ __forceinline__ void cp16(uint32_t dst, const void* src) {
    asm volatile("cp.async.cg.shared.global [%0], [%1], 16;" :: "r"(dst), "l"(src));
}
__device__ __forceinline__ void mbar_init(uint32_t a, uint32_t cnt) {
    asm volatile("mbarrier.init.shared.b64 [%0], %1;" :: "r"(a), "r"(cnt) : "memory");
}
// NOINC variant: consumes the pre-initialized arrival count (the default
// variant increments expected-count first => net zero => deadlock, cf. R11).
__device__ __forceinline__ void cp_async_arrive_noinc(uint32_t a) {
    asm volatile("cp.async.mbarrier.arrive.noinc.shared.b64 [%0];" :: "r"(a) : "memory");
}
__device__ __forceinline__ void mbar_arrive(uint32_t a) {
    asm volatile("mbarrier.arrive.shared.b64 _, [%0];" :: "r"(a) : "memory");
}
#define MBARRIER_WAIT_PARITY(mbar_smem_addr, phase_parity) do { \
    uint32_t _mbar = (uint32_t)(mbar_smem_addr); \
    uint32_t _parity = (uint32_t)(phase_parity); \
    uint32_t _done; \
    asm volatile( \
        "{\n\t.reg .pred p;\n\t" \
        "mbarrier.try_wait.parity.acquire.cta.shared::cta.b64 p, [%1], %2;\n\t" \
        "selp.b32 %0, 1, 0, p;\n\t}" \
        : "=r"(_done) : "r"(_mbar), "r"(_parity) : "memory"); \
    if (!_done) { \
        asm volatile( \
            "{\n\t.reg .pred P1;\n\t" \
            "WAIT_LOOP_%=:\n\t" \
            "mbarrier.try_wait.parity.acquire.cta.shared::cta.b64 P1, [%0], %1, 0x989680;\n\t" \
            "@P1 bra.uni WAIT_DONE_%=;\n\t" \
            "bra.uni WAIT_LOOP_%=;\n\t" \
            "WAIT_DONE_%=:\n\t}" \
            :: "r"(_mbar), "r"(_parity) : "memory"); \
    } \
} while(0)

__device__ __forceinline__ void ldsm_x4(uint32_t* r, uint32_t addr) {
    asm volatile("ldmatrix.sync.aligned.m8n8.x4.shared.b16 {%0,%1,%2,%3}, [%4];"
        : "=r"(r[0]), "=r"(r[1]), "=r"(r[2]), "=r"(r[3]) : "r"(addr));
}
__device__ __forceinline__ void mma16816(float* d, const uint32_t* a, const uint32_t* b) {
    asm volatile("mma.sync.aligned.m16n8k16.row.col.f32.bf16.bf16.f32 "
        "{%0,%1,%2,%3}, {%4,%5,%6,%7}, {%8,%9}, {%0,%1,%2,%3};"
        : "+f"(d[0]), "+f"(d[1]), "+f"(d[2]), "+f"(d[3])
        : "r"(a[0]), "r"(a[1]), "r"(a[2]), "r"(a[3]), "r"(b[0]), "r"(b[1]));
}
__device__ __forceinline__ void split2(float a, float b, uint32_t& hi2, uint32_t& lo2) {
    __nv_bfloat16 ha = __float2bfloat16(a);
    __nv_bfloat16 hb = __float2bfloat16(b);
    __nv_bfloat16 la = __float2bfloat16(a - __bfloat162float(ha));
    __nv_bfloat16 lb = __float2bfloat16(b - __bfloat162float(hb));
    __nv_bfloat162 h; h.x = ha; h.y = hb;
    __nv_bfloat162 l; l.x = la; l.y = lb;
    hi2 = *(uint32_t*)&h;
    lo2 = *(uint32_t*)&l;
}

// ---------------------------------------------------------------------------
// Async-pipeline mainloop: 128x128 block tile, K-chunk 16, 4-stage mbarrier
// pipeline (no __syncthreads in the loop), 8 warps (4x2), warp 32x64, occ 2.
// Rows padded to 48 B: 16B-aligned cp.async dst AND conflict-free ldmatrix.
// Empty barriers use ONE arrive per warp (count 8) to cut barrier traffic 32x.
// ---------------------------------------------------------------------------
#define KC     16
#define SROW   48                        // bytes per smem row
#define TILEB  (128 * SROW)              // 6144 B
#define STAGEB (4 * TILEB)               // 24576 B (Ahi, Alo, Bhi, Blo)
#define NSTAGE 4
#define MB_OFF (NSTAGE * STAGEB)         // 98304
#define GEMM_SMEM (MB_OFF + 64)          // + mbarriers

#define GEMM_MAINLOOP(Ahi_p, Alo_p, Bhi_p, Blo_p, Kdim)                               \
    const uint32_t mbF = sbase + MB_OFF;        /* full[0..3]  */                      \
    const uint32_t mbE = sbase + MB_OFF + 32;   /* empty[0..3] */                      \
    if (tid == 0) {                                                                    \
        _Pragma("unroll")                                                              \
        for (int s = 0; s < NSTAGE; ++s) {                                             \
            mbar_init(mbF + s * 8, 256);                                               \
            mbar_init(mbE + s * 8, 8);     /* one arrive per warp */                   \
        }                                                                              \
    }                                                                                  \
    __syncthreads();                                                                   \
    const int ldrow = tid >> 1, ldhalf = tid & 1;                                      \
    auto load_chunk = [&](int c, int stage) {                                          \
        const uint32_t st = sbase + stage * STAGEB;                                    \
        const long long kOff = (long long)c * KC;                                      \
        const __nv_bfloat16* srcs[4] = { Ahi_p, Alo_p, Bhi_p, Blo_p };                 \
        _Pragma("unroll")                                                              \
        for (int t = 0; t < 4; ++t) {                                                  \
            const int rB = (t < 2) ? rowBase : colBase;                                \
            cp16(st + t * TILEB + ldrow * SROW + ldhalf * 16,                          \
                 srcs[t] + (long long)(rB + ldrow) * (Kdim) + kOff + ldhalf * 8);      \
        }                                                                              \
    };                                                                                 \
    const uint32_t aRowOff = (uint32_t)(lid & 15) * SROW + (uint32_t)(lid >> 4) * 16;  \
    const uint32_t bRowOff = ((uint32_t)(lid & 7) + ((uint32_t)(lid >> 4) & 1) * 8) * SROW \
                           + (((uint32_t)(lid >> 3) & 1)) * 16;                        \
    const int nChunks = (Kdim) / KC;                                                   \
    _Pragma("unroll")                                                                  \
    for (int pc = 0; pc < 3; ++pc) {                                                   \
        if (pc < nChunks) { load_chunk(pc, pc); cp_async_arrive_noinc(mbF + pc * 8); } \
    }                                                                                  \
    for (int c = 0; c < nChunks; ++c) {                                                \
        const int s = c & 3;                                                           \
        MBARRIER_WAIT_PARITY(mbF + s * 8, (uint32_t)((c >> 2) & 1));                   \
        const uint32_t st = sbase + s * STAGEB;                                        \
        const uint32_t aHiB = st + 0 * TILEB + (uint32_t)(wm * 32) * SROW + aRowOff;   \
        const uint32_t aLoB = st + 1 * TILEB + (uint32_t)(wm * 32) * SROW + aRowOff;   \
        const uint32_t bHiB = st + 2 * TILEB + (uint32_t)(wn * 64) * SROW + bRowOff;   \
        const uint32_t bLoB = st + 3 * TILEB + (uint32_t)(wn * 64) * SROW + bRowOff;   \
        uint32_t ah[2][4], al[2][4];                                                   \
        ldsm_x4(ah[0], aHiB);                                                          \
        ldsm_x4(ah[1], aHiB + 16 * SROW);                                              \
        ldsm_x4(al[0], aLoB);                                                          \
        ldsm_x4(al[1], aLoB + 16 * SROW);                                              \
        uint32_t rhc[4], rlc[4], rhn[4], rln[4];                                       \
        ldsm_x4(rhc, bHiB);                                                            \
        ldsm_x4(rlc, bLoB);                                                            \
        _Pragma("unroll")                                                              \
        for (int p = 0; p < 4; ++p) {                                                  \
            if (p < 3) {                                                               \
                ldsm_x4(rhn, bHiB + (uint32_t)((p + 1) * 16) * SROW);                  \
                ldsm_x4(rln, bLoB + (uint32_t)((p + 1) * 16) * SROW);                  \
            }                                                                          \
            uint32_t bh0[2] = { rhc[0], rhc[1] }, bh1[2] = { rhc[2], rhc[3] };         \
            uint32_t bl0[2] = { rlc[0], rlc[1] }, bl1[2] = { rlc[2], rlc[3] };         \
            float* a00 = acc[0][p * 2];                                                \
            float* a10 = acc[1][p * 2];                                                \
            float* a01 = acc[0][p * 2 + 1];                                            \
            float* a11 = acc[1][p * 2 + 1];                                            \
            mma16816(a00, ah[0], bh0);                                                 \
            mma16816(a10, ah[1], bh0);                                                 \
            mma16816(a01, ah[0], bh1);                                                 \
            mma16816(a11, ah[1], bh1);                                                 \
            mma16816(a00, ah[0], bl0);                                                 \
            mma16816(a10, ah[1], bl0);                                                 \
            mma16816(a01, ah[0], bl1);                                                 \
            mma16816(a11, ah[1], bl1);                                                 \
            mma16816(a00, al[0], bh0);                                                 \
            mma16816(a10, al[1], bh0);                                                 \
            mma16816(a01, al[0], bh1);                                                 \
            mma16816(a11, al[1], bh1);                                                 \
            if (p < 3) {                                                               \
                rhc[0] = rhn[0]; rhc[1] = rhn[1]; rhc[2] = rhn[2]; rhc[3] = rhn[3];    \
                rlc[0] = rln[0]; rlc[1] = rln[1]; rlc[2] = rln[2]; rlc[3] = rln[3];    \
            }                                                                          \
        }                                                                              \
        __syncwarp();                                                                  \
        if (lid == 0) mbar_arrive(mbE + s * 8);  /* warp's stage-s reads done */       \
        if (c + 3 < nChunks) {                                                         \
            const int s3 = (c + 3) & 3;                                                \
            if (c >= 1) MBARRIER_WAIT_PARITY(mbE + s3 * 8,                             \
                                             (uint32_t)(((c - 1) >> 2) & 1));          \
            load_chunk(c + 3, s3);                                                     \
            cp_async_arrive_noinc(mbF + s3 * 8);                                       \
        }                                                                              \
    }

// ---------------------------------------------------------------------------
// Merged projection kernel: grid.z selects Q(0)/K(1)/V(2).
// ---------------------------------------------------------------------------
__global__ __launch_bounds__(256, 2)
void proj_mma(const __nv_bfloat16* __restrict__ xhi, const __nv_bfloat16* __restrict__ xlo,
              const __nv_bfloat16* __restrict__ Wqh, const __nv_bfloat16* __restrict__ Wql,
              const __nv_bfloat16* __restrict__ Wkh, const __nv_bfloat16* __restrict__ Wkl,
              const __nv_bfloat16* __restrict__ Wvh, const __nv_bfloat16* __restrict__ Wvl,
              const float* __restrict__ bq, const float* __restrict__ bk,
              const float* __restrict__ bv,
              __nv_bfloat16* __restrict__ Qh, __nv_bfloat16* __restrict__ Ql,
              __nv_bfloat16* __restrict__ Kh, __nv_bfloat16* __restrict__ Kl,
              __nv_bfloat16* __restrict__ Vth, __nv_bfloat16* __restrict__ Vtl)
{
    extern __shared__ char smem[];
    const uint32_t sbase = smem_to_u32(smem);
    const int tid = threadIdx.x;
    const int wid = tid >> 5;
    const int lid = tid & 31;
    const int wm  = wid & 3;
    const int wn  = wid >> 2;
    const int rowBase = blockIdx.y * 128;
    const int colBase = blockIdx.x * 128;
    const int z = blockIdx.z;          // 0=Q 1=K 2=V

    const __nv_bfloat16* Bh = (z == 0) ? Wqh : (z == 1) ? Wkh : Wvh;
    const __nv_bfloat16* Bl = (z == 0) ? Wql : (z == 1) ? Wkl : Wvl;
    const float* bias       = (z == 0) ? bq  : (z == 1) ? bk  : bv;

    float acc[2][8][4];
#pragma unroll
    for (int i = 0; i < 2; ++i)
#pragma unroll
        for (int j = 0; j < 8; ++j)
#pragma unroll
            for (int q = 0; q < 4; ++q) acc[i][j][q] = 0.0f;

    GEMM_MAINLOOP(xhi, xlo, Bh, Bl, DIM)

    const int g = lid >> 2, t = lid & 3;
    if (z < 2) {
        __nv_bfloat16* Chi = (z == 0) ? Qh : Kh;
        __nv_bfloat16* Clo = (z == 0) ? Ql : Kl;
#pragma unroll
        for (int i = 0; i < 2; ++i) {
            const int r0 = rowBase + wm * 32 + i * 16 + g;
            const int r1 = r0 + 8;
#pragma unroll
            for (int j = 0; j < 8; ++j) {
                const int col = colBase + wn * 64 + j * 8 + t * 2;
                float b0 = __ldg(bias + col), b1 = __ldg(bias + col + 1);
                uint32_t h2, l2;
                split2(acc[i][j][0] + b0, acc[i][j][1] + b1, h2, l2);
                *(uint32_t*)(Chi + (long long)r0 * DIM + col) = h2;
                *(uint32_t*)(Clo + (long long)r0 * DIM + col) = l2;
                split2(acc[i][j][2] + b0, acc[i][j][3] + b1, h2, l2);
                *(uint32_t*)(Chi + (long long)r1 * DIM + col) = h2;
                *(uint32_t*)(Clo + (long long)r1 * DIM + col) = l2;
            }
        }
    } else {
        // V: transposed split output Vt[DIM, SEQ] per batch, smem-staged
        __syncthreads();
        float* buf = (float*)smem;
#pragma unroll
        for (int i = 0; i < 2; ++i) {
            const int lr = wm * 32 + i * 16 + g;
#pragma unroll
            for (int j = 0; j < 8; ++j) {
                const int lc = wn * 64 + j * 8 + t * 2;
                float b0 = __ldg(bias + colBase + lc);
                float b1 = __ldg(bias + colBase + lc + 1);
                buf[lr * 129 + lc]           = acc[i][j][0] + b0;
                buf[lr * 129 + lc + 1]       = acc[i][j][1] + b1;
                buf[(lr + 8) * 129 + lc]     = acc[i][j][2] + b0;
                buf[(lr + 8) * 129 + lc + 1] = acc[i][j][3] + b1;
            }
        }
        __syncthreads();
        const int dcol = tid >> 1;
        const int sb2  = (tid & 1) * 64;
        const int bIdx = rowBase >> 11;
        const int srow0 = rowBase & (SEQ - 1);
        long long o = (long long)bIdx * DIM * SEQ + (long long)(colBase + dcol) * SEQ
                    + srow0 + sb2;
        __nv_bfloat16* Hb = Vth + o;
        __nv_bfloat16* Lb = Vtl + o;
#pragma unroll
        for (int s2 = 0; s2 < 64; s2 += 2) {
            float v0 = buf[(sb2 + s2) * 129 + dcol];
            float v1 = buf[(sb2 + s2 + 1) * 129 + dcol];
            uint32_t h2, l2;
            split2(v0, v1, h2, l2);
            *(uint32_t*)(Hb + s2) = h2;
            *(uint32_t*)(Lb + s2) = l2;
        }
    }
}

// ---------------------------------------------------------------------------
// Scores kernel: S = Q K^T, epilogue exp + split + atomic row sums.
// ---------------------------------------------------------------------------
__global__ __launch_bounds__(256, 2)
void scores_mma(const __nv_bfloat16* __restrict__ Qh, const __nv_bfloat16* __restrict__ Ql,
                const __nv_bfloat16* __restrict__ Kh, const __nv_bfloat16* __restrict__ Kl,
                __nv_bfloat16* __restrict__ Ph, __nv_bfloat16* __restrict__ Pl,
                float* __restrict__ rs)
{
    extern __shared__ char smem[];
    const uint32_t sbase = smem_to_u32(smem);
    const int tid = threadIdx.x;
    const int wid = tid >> 5;
    const int lid = tid & 31;
    const int wm  = wid & 3;
    const int wn  = wid >> 2;
    const int rowBase = blockIdx.y * 128;
    const int colBase = blockIdx.x * 128;
    const int z = blockIdx.z;

    const __nv_bfloat16* Ahi_p = Qh + (long long)z * SEQ * DIM;
    const __nv_bfloat16* Alo_p = Ql + (long long)z * SEQ * DIM;
    const __nv_bfloat16* Bhi_p = Kh + (long long)z * SEQ * DIM;
    const __nv_bfloat16* Blo_p = Kl + (long long)z * SEQ * DIM;

    float acc[2][8][4];
#pragma unroll
    for (int i = 0; i < 2; ++i)
#pragma unroll
        for (int j = 0; j < 8; ++j)
#pragma unroll
            for (int q = 0; q < 4; ++q) acc[i][j][q] = 0.0f;

    GEMM_MAINLOOP(Ahi_p, Alo_p, Bhi_p, Blo_p, DIM)

    const int g = lid >> 2, t = lid & 3;
    __nv_bfloat16* Hb = Ph + (long long)z * SEQ * SEQ;
    __nv_bfloat16* Lb = Pl + (long long)z * SEQ * SEQ;
#pragma unroll
    for (int i = 0; i < 2; ++i) {
        const int r0 = rowBase + wm * 32 + i * 16 + g;
        const int r1 = r0 + 8;
        float sum0 = 0.f, sum1 = 0.f;
#pragma unroll
        for (int j = 0; j < 8; ++j) {
            const int col = colBase + wn * 64 + j * 8 + t * 2;
            float e00 = __expf(acc[i][j][0]);
            float e01 = __expf(acc[i][j][1]);
            float e10 = __expf(acc[i][j][2]);
            float e11 = __expf(acc[i][j][3]);
            sum0 += e00 + e01;
            sum1 += e10 + e11;
            uint32_t h2, l2;
            split2(e00, e01, h2, l2);
            *(uint32_t*)(Hb + (long long)r0 * SEQ + col) = h2;
            *(uint32_t*)(Lb + (long long)r0 * SEQ + col) = l2;
            split2(e10, e11, h2, l2);
            *(uint32_t*)(Hb + (long long)r1 * SEQ + col) = h2;
            *(uint32_t*)(Lb + (long long)r1 * SEQ + col) = l2;
        }
        sum0 += __shfl_xor_sync(0xffffffffu, sum0, 1);
        sum0 += __shfl_xor_sync(0xffffffffu, sum0, 2);
        sum1 += __shfl_xor_sync(0xffffffffu, sum1, 1);
        sum1 += __shfl_xor_sync(0xffffffffu, sum1, 2);
        if (t == 0) {
            atomicAdd(rs + (long long)z * SEQ + r0, sum0);
            atomicAdd(rs + (long long)z * SEQ + r1, sum1);
        }
    }
}

// ---------------------------------------------------------------------------
// PV kernel: out = (E V) / rowsum
// ---------------------------------------------------------------------------
__global__ __launch_bounds__(256, 2)
void pv_mma(const __nv_bfloat16* __restrict__ Ph, const __nv_bfloat16* __restrict__ Pl,
            const __nv_bfloat16* __restrict__ Vth, const __nv_bfloat16* __restrict__ Vtl,
            const float* __restrict__ rs, float* __restrict__ out)
{
    extern __shared__ char smem[];
    const uint32_t sbase = smem_to_u32(smem);
    const int tid = threadIdx.x;
    const int wid = tid >> 5;
    const int lid = tid & 31;
    const int wm  = wid & 3;
    const int wn  = wid >> 2;
    const int rowBase = blockIdx.y * 128;
    const int colBase = blockIdx.x * 128;
    const int z = blockIdx.z;

    const __nv_bfloat16* Ahi_p = Ph + (long long)z * SEQ * SEQ;
    const __nv_bfloat16* Alo_p = Pl + (long long)z * SEQ * SEQ;
    const __nv_bfloat16* Bhi_p = Vth + (long long)z * DIM * SEQ;
    const __nv_bfloat16* Blo_p = Vtl + (long long)z * DIM * SEQ;

    float acc[2][8][4];
#pragma unroll
    for (int i = 0; i < 2; ++i)
#pragma unroll
        for (int j = 0; j < 8; ++j)
#pragma unroll
            for (int q = 0; q < 4; ++q) acc[i][j][q] = 0.0f;

    GEMM_MAINLOOP(Ahi_p, Alo_p, Bhi_p, Blo_p, SEQ)

    const int g = lid >> 2, t = lid & 3;
    float* C_b = out + (long long)z * SEQ * DIM;
#pragma unroll
    for (int i = 0; i < 2; ++i) {
        const int r0 = rowBase + wm * 32 + i * 16 + g;
        const int r1 = r0 + 8;
        const float inv0 = 1.0f / __ldg(rs + (long long)z * SEQ + r0);
        const float inv1 = 1.0f / __ldg(rs + (long long)z * SEQ + r1);
#pragma unroll
        for (int j = 0; j < 8; ++j) {
            const int col = colBase + wn * 64 + j * 8 + t * 2;
            *(float2*)(C_b + (long long)r0 * DIM + col) =
                make_float2(acc[i][j][0] * inv0, acc[i][j][1] * inv0);
            *(float2*)(C_b + (long long)r1 * DIM + col) =
                make_float2(acc[i][j][2] * inv1, acc[i][j][3] * inv1);
        }
    }
}

// ---------------------------------------------------------------------------
// Split fp32 -> (hi, lo) bf16 (x) + zero the rowsum buffer (fused)
// ---------------------------------------------------------------------------
__global__ __launch_bounds__(256)
void split_zero_kernel(const float4* __restrict__ in, uint2* __restrict__ hi,
                       uint2* __restrict__ lo, float* __restrict__ rs, long long n4)
{
    long long i = (long long)blockIdx.x * 256 + threadIdx.x;
    if (i < ROWS) rs[i] = 0.0f;
    if (i >= n4) return;
    float4 v = in[i];
    uint32_t h01, l01, h23, l23;
    split2(v.x, v.y, h01, l01);
    split2(v.z, v.w, h23, l23);
    uint2 ho, lo2;
    ho.x = h01; ho.y = h23;
    lo2.x = l01; lo2.y = l23;
    hi[i] = ho;
    lo[i] = lo2;
}

// Transpose fp32 [DIM,DIM] -> bf16 hi/lo, all three weights in one launch.
__global__ __launch_bounds__(256)
void transpose_split3_kernel(const float* __restrict__ Wq, const float* __restrict__ Wk,
                             const float* __restrict__ Wv,
                             __nv_bfloat16* __restrict__ Qh, __nv_bfloat16* __restrict__ Ql,
                             __nv_bfloat16* __restrict__ Kh, __nv_bfloat16* __restrict__ Kl,
                             __nv_bfloat16* __restrict__ Vh, __nv_bfloat16* __restrict__ Vl)
{
    __shared__ float t[32][33];
    const int z = blockIdx.z;
    const float* in = (z == 0) ? Wq : (z == 1) ? Wk : Wv;
    __nv_bfloat16* hi = (z == 0) ? Qh : (z == 1) ? Kh : Vh;
    __nv_bfloat16* lo = (z == 0) ? Ql : (z == 1) ? Kl : Vl;

    const int tx = threadIdx.x, ty = threadIdx.y;
    const int x = blockIdx.x * 32 + tx;
    const int y0 = blockIdx.y * 32;
#pragma unroll
    for (int j = 0; j < 4; ++j)
        t[ty + j * 8][tx] = in[(long long)(y0 + ty + j * 8) * DIM + x];
    __syncthreads();

    const int ox = blockIdx.y * 32 + tx;
    const int oy0 = blockIdx.x * 32;
#pragma unroll
    for (int j = 0; j < 4; ++j) {
        float v = t[tx][ty + j * 8];
        __nv_bfloat16 h = __float2bfloat16(v);
        __nv_bfloat16 l = __float2bfloat16(v - __bfloat162float(h));
        long long o = (long long)(oy0 + ty + j * 8) * DIM + ox;
        hi[o] = h;
        lo[o] = l;
    }
}

// ---------------------------------------------------------------------------
extern "C" void kernel_launch(void* const* d_in, const int* in_sizes, int n_in,
                              void* d_out, int out_size)
{
    const float* x  = (const float*)d_in[0];
    const float* Wq = (const float*)d_in[1];
    const float* bq = (const float*)d_in[2];
    const float* Wk = (const float*)d_in[3];
    const float* bk = (const float*)d_in[4];
    const float* Wv = (const float*)d_in[5];
    const float* bv = (const float*)d_in[6];
    float* out = (float*)d_out;

    __nv_bfloat16 *xhi, *xlo, *Wqthi, *Wqtlo, *Wkthi, *Wktlo, *Wvthi, *Wvtlo;
    __nv_bfloat16 *Qhi, *Qlo, *Khi, *Klo, *Vthi, *Vtlo, *Phi, *Plo;
    float *rs;
    cudaGetSymbolAddress((void**)&xhi, g_xhi);     cudaGetSymbolAddress((void**)&xlo, g_xlo);
    cudaGetSymbolAddress((void**)&Wqthi, g_Wqthi); cudaGetSymbolAddress((void**)&Wqtlo, g_Wqtlo);
    cudaGetSymbolAddress((void**)&Wkthi, g_Wkthi); cudaGetSymbolAddress((void**)&Wktlo, g_Wktlo);
    cudaGetSymbolAddress((void**)&Wvthi, g_Wvthi); cudaGetSymbolAddress((void**)&Wvtlo, g_Wvtlo);
    cudaGetSymbolAddress((void**)&Qhi, g_Qhi); cudaGetSymbolAddress((void**)&Qlo, g_Qlo);
    cudaGetSymbolAddress((void**)&Khi, g_Khi); cudaGetSymbolAddress((void**)&Klo, g_Klo);
    cudaGetSymbolAddress((void**)&Vthi, g_Vthi); cudaGetSymbolAddress((void**)&Vtlo, g_Vtlo);
    cudaGetSymbolAddress((void**)&Phi, g_Phi); cudaGetSymbolAddress((void**)&Plo, g_Plo);
    cudaGetSymbolAddress((void**)&rs, g_rowsum);

    cudaFuncSetAttribute(proj_mma,   cudaFuncAttributeMaxDynamicSharedMemorySize, GEMM_SMEM);
    cudaFuncSetAttribute(scores_mma, cudaFuncAttributeMaxDynamicSharedMemorySize, GEMM_SMEM);
    cudaFuncSetAttribute(pv_mma,     cudaFuncAttributeMaxDynamicSharedMemorySize, GEMM_SMEM);

    // 1) Split x (+ zero rowsums)
    {
        long long n4 = (long long)ROWS * DIM / 4;
        split_zero_kernel<<<(unsigned)((n4 + 255) / 256), 256>>>(
            (const float4*)x, (uint2*)xhi, (uint2*)xlo, rs, n4);
    }
    // 2) Transpose+split all three weights in one launch
    transpose_split3_kernel<<<dim3(DIM / 32, DIM / 32, 3), dim3(32, 8)>>>(
        Wq, Wk, Wv, Wqthi, Wqtlo, Wkthi, Wktlo, Wvthi, Wvtlo);

    // 3) All three projections in ONE launch (z: 0=Q, 1=K, 2=V)
    {
        dim3 g(DIM / 128, ROWS / 128, 3);
        proj_mma<<<g, 256, GEMM_SMEM>>>(xhi, xlo,
                                        Wqthi, Wqtlo, Wkthi, Wktlo, Wvthi, Wvtlo,
                                        bq, bk, bv,
                                        Qhi, Qlo, Khi, Klo, Vthi, Vtlo);
    }
    // 4) Scores with fused exp + split + rowsum
    {
        dim3 g(SEQ / 128, SEQ / 128, BATCH);
        scores_mma<<<g, 256, GEMM_SMEM>>>(Qhi, Qlo, Khi, Klo, Phi, Plo, rs);
    }
    // 5) Out: out[b] = (E[b] @ V[b]) / rowsum
    {
        dim3 g(DIM / 128, SEQ / 128, BATCH);
        pv_mma<<<g, 256, GEMM_SMEM>>>(Phi, Plo, Vthi, Vtlo, rs, out);
    }
}

// round 15
// speedup vs baseline: 1.0286x; 1.0286x over previous
#include <cuda_runtime.h>
#include <cuda_bf16.h>
#include <cstdint>

// Problem constants: B=8, N=2048, D=DQ=DV=1024
#define BATCH 8
#define SEQ   2048
#define DIM   1024
#define ROWS  (BATCH * SEQ)        // 16384

// ---------------------------------------------------------------------------
// Device scratch
// ---------------------------------------------------------------------------
__device__ __nv_bfloat16 g_xhi[(size_t)ROWS * DIM];
__device__ __nv_bfloat16 g_xlo[(size_t)ROWS * DIM];
__device__ __nv_bfloat16 g_Wqthi[(size_t)DIM * DIM], g_Wqtlo[(size_t)DIM * DIM];
__device__ __nv_bfloat16 g_Wkthi[(size_t)DIM * DIM], g_Wktlo[(size_t)DIM * DIM];
__device__ __nv_bfloat16 g_Wvthi[(size_t)DIM * DIM], g_Wvtlo[(size_t)DIM * DIM];
__device__ __nv_bfloat16 g_Qhi[(size_t)ROWS * DIM], g_Qlo[(size_t)ROWS * DIM];
__device__ __nv_bfloat16 g_Khi[(size_t)ROWS * DIM], g_Klo[(size_t)ROWS * DIM];
__device__ __nv_bfloat16 g_Vthi[(size_t)BATCH * DIM * SEQ], g_Vtlo[(size_t)BATCH * DIM * SEQ];
__device__ __nv_bfloat16 g_Phi[(size_t)BATCH * SEQ * SEQ], g_Plo[(size_t)BATCH * SEQ * SEQ];
__device__ float g_rowsum[(size_t)ROWS];

// ---------------------------------------------------------------------------
// PTX helpers (portable sm_80+: mma.sync / ldmatrix / cp.async / mbarrier)
// ---------------------------------------------------------------------------
__device__ __forceinline__ uint32_t smem_to_u32(const void* p) {
    uint32_t a;
    asm("{ .reg .u64 t; cvta.to.shared.u64 t, %1; cvt.u32.u64 %0, t; }" : "=r"(a) : "l"(p));
    return a;
}
__device__ __forceinline__ void cp16(uint32_t dst, const void* src) {
    asm volatile("cp.async.cg.shared.global [%0], [%1], 16;" :: "r"(dst), "l"(src));
}
__device__ __forceinline__ void mbar_init(uint32_t a, uint32_t cnt) {
    asm volatile("mbarrier.init.shared.b64 [%0], %1;" :: "r"(a), "r"(cnt) : "memory");
}
// NOINC variant: consumes the pre-initialized arrival count (the default
// variant increments expected-count first => net zero => deadlock, cf. R11).
__device__ __forceinline__ void cp_async_arrive_noinc(uint32_t a) {
    asm volatile("cp.async.mbarrier.arrive.noinc.shared.b64 [%0];" :: "r"(a) : "memory");
}
__device__ __forceinline__ void mbar_arrive(uint32_t a) {
    asm volatile("mbarrier.arrive.shared.b64 _, [%0];" :: "r"(a) : "memory");
}
#define MBARRIER_WAIT_PARITY(mbar_smem_addr, phase_parity) do { \
    uint32_t _mbar = (uint32_t)(mbar_smem_addr); \
    uint32_t _parity = (uint32_t)(phase_parity); \
    uint32_t _done; \
    asm volatile( \
        "{\n\t.reg .pred p;\n\t" \
        "mbarrier.try_wait.parity.acquire.cta.shared::cta.b64 p, [%1], %2;\n\t" \
        "selp.b32 %0, 1, 0, p;\n\t}" \
        : "=r"(_done) : "r"(_mbar), "r"(_parity) : "memory"); \
    if (!_done) { \
        asm volatile( \
            "{\n\t.reg .pred P1;\n\t" \
            "WAIT_LOOP_%=:\n\t" \
            "mbarrier.try_wait.parity.acquire.cta.shared::cta.b64 P1, [%0], %1, 0x989680;\n\t" \
            "@P1 bra.uni WAIT_DONE_%=;\n\t" \
            "bra.uni WAIT_LOOP_%=;\n\t" \
            "WAIT_DONE_%=:\n\t}" \
            :: "r"(_mbar), "r"(_parity) : "memory"); \
    } \
} while(0)

__device__ __forceinline__ void ldsm_x4(uint32_t* r, uint32_t addr) {
    asm volatile("ldmatrix.sync.aligned.m8n8.x4.shared.b16 {%0,%1,%2,%3}, [%4];"
        : "=r"(r[0]), "=r"(r[1]), "=r"(r[2]), "=r"(r[3]) : "r"(addr));
}
__device__ __forceinline__ void mma16816(float* d, const uint32_t* a, const uint32_t* b) {
    asm volatile("mma.sync.aligned.m16n8k16.row.col.f32.bf16.bf16.f32 "
        "{%0,%1,%2,%3}, {%4,%5,%6,%7}, {%8,%9}, {%0,%1,%2,%3};"
        : "+f"(d[0]), "+f"(d[1]), "+f"(d[2]), "+f"(d[3])
        : "r"(a[0]), "r"(a[1]), "r"(a[2]), "r"(a[3]), "r"(b[0]), "r"(b[1]));
}
__device__ __forceinline__ void split2(float a, float b, uint32_t& hi2, uint32_t& lo2) {
    __nv_bfloat16 ha = __float2bfloat16(a);
    __nv_bfloat16 hb = __float2bfloat16(b);
    __nv_bfloat16 la = __float2bfloat16(a - __bfloat162float(ha));
    __nv_bfloat16 lb = __float2bfloat16(b - __bfloat162float(hb));
    __nv_bfloat162 h; h.x = ha; h.y = hb;
    __nv_bfloat162 l; l.x = la; l.y = lb;
    hi2 = *(uint32_t*)&h;
    lo2 = *(uint32_t*)&l;
}

// ---------------------------------------------------------------------------
// Async-pipeline mainloop: 128x128 block tile, K-chunk 16, 4-stage mbarrier
// pipeline (no __syncthreads in the loop), 8 warps (4x2), warp 32x64, occ 2.
// Rows padded to 48 B: 16B-aligned cp.async dst AND conflict-free ldmatrix.
// ---------------------------------------------------------------------------
#define KC     16
#define SROW   48                        // bytes per smem row
#define TILEB  (128 * SROW)              // 6144 B
#define STAGEB (4 * TILEB)               // 24576 B (Ahi, Alo, Bhi, Blo)
#define NSTAGE 4
#define MB_OFF (NSTAGE * STAGEB)         // 98304
#define GEMM_SMEM (MB_OFF + 64)          // + mbarriers

#define GEMM_MAINLOOP(Ahi_p, Alo_p, Bhi_p, Blo_p, Kdim)                               \
    const uint32_t mbF = sbase + MB_OFF;        /* full[0..3]  */                      \
    const uint32_t mbE = sbase + MB_OFF + 32;   /* empty[0..3] */                      \
    if (tid == 0) {                                                                    \
        _Pragma("unroll")                                                              \
        for (int s = 0; s < NSTAGE; ++s) {                                             \
            mbar_init(mbF + s * 8, 256);                                               \
            mbar_init(mbE + s * 8, 256);                                               \
        }                                                                              \
    }                                                                                  \
    __syncthreads();                                                                   \
    const int ldrow = tid >> 1, ldhalf = tid & 1;                                      \
    auto load_chunk = [&](int c, int stage) {                                          \
        const uint32_t st = sbase + stage * STAGEB;                                    \
        const long long kOff = (long long)c * KC;                                      \
        const __nv_bfloat16* srcs[4] = { Ahi_p, Alo_p, Bhi_p, Blo_p };                 \
        _Pragma("unroll")                                                              \
        for (int t = 0; t < 4; ++t) {                                                  \
            const int rB = (t < 2) ? rowBase : colBase;                                \
            cp16(st + t * TILEB + ldrow * SROW + ldhalf * 16,                          \
                 srcs[t] + (long long)(rB + ldrow) * (Kdim) + kOff + ldhalf * 8);      \
        }                                                                              \
    };                                                                                 \
    const uint32_t aRowOff = (uint32_t)(lid & 15) * SROW + (uint32_t)(lid >> 4) * 16;  \
    const uint32_t bRowOff = ((uint32_t)(lid & 7) + ((uint32_t)(lid >> 4) & 1) * 8) * SROW \
                           + (((uint32_t)(lid >> 3) & 1)) * 16;                        \
    const int nChunks = (Kdim) / KC;                                                   \
    _Pragma("unroll")                                                                  \
    for (int pc = 0; pc < 3; ++pc) {                                                   \
        if (pc < nChunks) { load_chunk(pc, pc); cp_async_arrive_noinc(mbF + pc * 8); } \
    }                                                                                  \
    for (int c = 0; c < nChunks; ++c) {                                                \
        const int s = c & 3;                                                           \
        MBARRIER_WAIT_PARITY(mbF + s * 8, (uint32_t)((c >> 2) & 1));                   \
        const uint32_t st = sbase + s * STAGEB;                                        \
        const uint32_t aHiB = st + 0 * TILEB + (uint32_t)(wm * 32) * SROW + aRowOff;   \
        const uint32_t aLoB = st + 1 * TILEB + (uint32_t)(wm * 32) * SROW + aRowOff;   \
        const uint32_t bHiB = st + 2 * TILEB + (uint32_t)(wn * 64) * SROW + bRowOff;   \
        const uint32_t bLoB = st + 3 * TILEB + (uint32_t)(wn * 64) * SROW + bRowOff;   \
        uint32_t ah[2][4], al[2][4];                                                   \
        ldsm_x4(ah[0], aHiB);                                                          \
        ldsm_x4(ah[1], aHiB + 16 * SROW);                                              \
        ldsm_x4(al[0], aLoB);                                                          \
        ldsm_x4(al[1], aLoB + 16 * SROW);                                              \
        uint32_t rhc[4], rlc[4], rhn[4], rln[4];                                       \
        ldsm_x4(rhc, bHiB);                                                            \
        ldsm_x4(rlc, bLoB);                                                            \
        _Pragma("unroll")                                                              \
        for (int p = 0; p < 4; ++p) {                                                  \
            if (p < 3) {                                                               \
                ldsm_x4(rhn, bHiB + (uint32_t)((p + 1) * 16) * SROW);                  \
                ldsm_x4(rln, bLoB + (uint32_t)((p + 1) * 16) * SROW);                  \
            }                                                                          \
            uint32_t bh0[2] = { rhc[0], rhc[1] }, bh1[2] = { rhc[2], rhc[3] };         \
            uint32_t bl0[2] = { rlc[0], rlc[1] }, bl1[2] = { rlc[2], rlc[3] };         \
            float* a00 = acc[0][p * 2];                                                \
            float* a10 = acc[1][p * 2];                                                \
            float* a01 = acc[0][p * 2 + 1];                                            \
            float* a11 = acc[1][p * 2 + 1];                                            \
            mma16816(a00, ah[0], bh0);                                                 \
            mma16816(a10, ah[1], bh0);                                                 \
            mma16816(a01, ah[0], bh1);                                                 \
            mma16816(a11, ah[1], bh1);                                                 \
            mma16816(a00, ah[0], bl0);                                                 \
            mma16816(a10, ah[1], bl0);                                                 \
            mma16816(a01, ah[0], bl1);                                                 \
            mma16816(a11, ah[1], bl1);                                                 \
            mma16816(a00, al[0], bh0);                                                 \
            mma16816(a10, al[1], bh0);                                                 \
            mma16816(a01, al[0], bh1);                                                 \
            mma16816(a11, al[1], bh1);                                                 \
            if (p < 3) {                                                               \
                rhc[0] = rhn[0]; rhc[1] = rhn[1]; rhc[2] = rhn[2]; rhc[3] = rhn[3];    \
                rlc[0] = rln[0]; rlc[1] = rln[1]; rlc[2] = rln[2]; rlc[3] = rln[3];    \
            }                                                                          \
        }                                                                              \
        mbar_arrive(mbE + s * 8);   /* my reads of stage s (chunk c) are done */       \
        if (c + 3 < nChunks) {                                                         \
            const int s3 = (c + 3) & 3;                                                \
            if (c >= 1) MBARRIER_WAIT_PARITY(mbE + s3 * 8,                             \
                                             (uint32_t)(((c - 1) >> 2) & 1));          \
            load_chunk(c + 3, s3);                                                     \
            cp_async_arrive_noinc(mbF + s3 * 8);                                       \
        }                                                                              \
    }

// ---------------------------------------------------------------------------
// Merged projection kernel: grid.z selects Q(0)/K(1)/V(2).
// ---------------------------------------------------------------------------
__global__ __launch_bounds__(256, 2)
void proj_mma(const __nv_bfloat16* __restrict__ xhi, const __nv_bfloat16* __restrict__ xlo,
              const __nv_bfloat16* __restrict__ Wqh, const __nv_bfloat16* __restrict__ Wql,
              const __nv_bfloat16* __restrict__ Wkh, const __nv_bfloat16* __restrict__ Wkl,
              const __nv_bfloat16* __restrict__ Wvh, const __nv_bfloat16* __restrict__ Wvl,
              const float* __restrict__ bq, const float* __restrict__ bk,
              const float* __restrict__ bv,
              __nv_bfloat16* __restrict__ Qh, __nv_bfloat16* __restrict__ Ql,
              __nv_bfloat16* __restrict__ Kh, __nv_bfloat16* __restrict__ Kl,
              __nv_bfloat16* __restrict__ Vth, __nv_bfloat16* __restrict__ Vtl)
{
    extern __shared__ char smem[];
    const uint32_t sbase = smem_to_u32(smem);
    const int tid = threadIdx.x;
    const int wid = tid >> 5;
    const int lid = tid & 31;
    const int wm  = wid & 3;
    const int wn  = wid >> 2;
    const int rowBase = blockIdx.y * 128;
    const int colBase = blockIdx.x * 128;
    const int z = blockIdx.z;          // 0=Q 1=K 2=V

    const __nv_bfloat16* Bh = (z == 0) ? Wqh : (z == 1) ? Wkh : Wvh;
    const __nv_bfloat16* Bl = (z == 0) ? Wql : (z == 1) ? Wkl : Wvl;
    const float* bias       = (z == 0) ? bq  : (z == 1) ? bk  : bv;

    float acc[2][8][4];
#pragma unroll
    for (int i = 0; i < 2; ++i)
#pragma unroll
        for (int j = 0; j < 8; ++j)
#pragma unroll
            for (int q = 0; q < 4; ++q) acc[i][j][q] = 0.0f;

    GEMM_MAINLOOP(xhi, xlo, Bh, Bl, DIM)

    const int g = lid >> 2, t = lid & 3;
    if (z < 2) {
        __nv_bfloat16* Chi = (z == 0) ? Qh : Kh;
        __nv_bfloat16* Clo = (z == 0) ? Ql : Kl;
#pragma unroll
        for (int i = 0; i < 2; ++i) {
            const int r0 = rowBase + wm * 32 + i * 16 + g;
            const int r1 = r0 + 8;
#pragma unroll
            for (int j = 0; j < 8; ++j) {
                const int col = colBase + wn * 64 + j * 8 + t * 2;
                float b0 = __ldg(bias + col), b1 = __ldg(bias + col + 1);
                uint32_t h2, l2;
                split2(acc[i][j][0] + b0, acc[i][j][1] + b1, h2, l2);
                *(uint32_t*)(Chi + (long long)r0 * DIM + col) = h2;
                *(uint32_t*)(Clo + (long long)r0 * DIM + col) = l2;
                split2(acc[i][j][2] + b0, acc[i][j][3] + b1, h2, l2);
                *(uint32_t*)(Chi + (long long)r1 * DIM + col) = h2;
                *(uint32_t*)(Clo + (long long)r1 * DIM + col) = l2;
            }
        }
    } else {
        // V: transposed split output Vt[DIM, SEQ] per batch, smem-staged
        __syncthreads();
        float* buf = (float*)smem;
#pragma unroll
        for (int i = 0; i < 2; ++i) {
            const int lr = wm * 32 + i * 16 + g;
#pragma unroll
            for (int j = 0; j < 8; ++j) {
                const int lc = wn * 64 + j * 8 + t * 2;
                float b0 = __ldg(bias + colBase + lc);
                float b1 = __ldg(bias + colBase + lc + 1);
                buf[lr * 129 + lc]           = acc[i][j][0] + b0;
                buf[lr * 129 + lc + 1]       = acc[i][j][1] + b1;
                buf[(lr + 8) * 129 + lc]     = acc[i][j][2] + b0;
                buf[(lr + 8) * 129 + lc + 1] = acc[i][j][3] + b1;
            }
        }
        __syncthreads();
        const int dcol = tid >> 1;
        const int sb2  = (tid & 1) * 64;
        const int bIdx = rowBase >> 11;
        const int srow0 = rowBase & (SEQ - 1);
        long long o = (long long)bIdx * DIM * SEQ + (long long)(colBase + dcol) * SEQ
                    + srow0 + sb2;
        __nv_bfloat16* Hb = Vth + o;
        __nv_bfloat16* Lb = Vtl + o;
#pragma unroll
        for (int s2 = 0; s2 < 64; s2 += 2) {
            float v0 = buf[(sb2 + s2) * 129 + dcol];
            float v1 = buf[(sb2 + s2 + 1) * 129 + dcol];
            uint32_t h2, l2;
            split2(v0, v1, h2, l2);
            *(uint32_t*)(Hb + s2) = h2;
            *(uint32_t*)(Lb + s2) = l2;
        }
    }
}

// ---------------------------------------------------------------------------
// Scores kernel: S = Q K^T, epilogue exp + split + atomic row sums.
// ---------------------------------------------------------------------------
__global__ __launch_bounds__(256, 2)
void scores_mma(const __nv_bfloat16* __restrict__ Qh, const __nv_bfloat16* __restrict__ Ql,
                const __nv_bfloat16* __restrict__ Kh, const __nv_bfloat16* __restrict__ Kl,
                __nv_bfloat16* __restrict__ Ph, __nv_bfloat16* __restrict__ Pl,
                float* __restrict__ rs)
{
    extern __shared__ char smem[];
    const uint32_t sbase = smem_to_u32(smem);
    const int tid = threadIdx.x;
    const int wid = tid >> 5;
    const int lid = tid & 31;
    const int wm  = wid & 3;
    const int wn  = wid >> 2;
    const int rowBase = blockIdx.y * 128;
    const int colBase = blockIdx.x * 128;
    const int z = blockIdx.z;

    const __nv_bfloat16* Ahi_p = Qh + (long long)z * SEQ * DIM;
    const __nv_bfloat16* Alo_p = Ql + (long long)z * SEQ * DIM;
    const __nv_bfloat16* Bhi_p = Kh + (long long)z * SEQ * DIM;
    const __nv_bfloat16* Blo_p = Kl + (long long)z * SEQ * DIM;

    float acc[2][8][4];
#pragma unroll
    for (int i = 0; i < 2; ++i)
#pragma unroll
        for (int j = 0; j < 8; ++j)
#pragma unroll
            for (int q = 0; q < 4; ++q) acc[i][j][q] = 0.0f;

    GEMM_MAINLOOP(Ahi_p, Alo_p, Bhi_p, Blo_p, DIM)

    const int g = lid >> 2, t = lid & 3;
    __nv_bfloat16* Hb = Ph + (long long)z * SEQ * SEQ;
    __nv_bfloat16* Lb = Pl + (long long)z * SEQ * SEQ;
#pragma unroll
    for (int i = 0; i < 2; ++i) {
        const int r0 = rowBase + wm * 32 + i * 16 + g;
        const int r1 = r0 + 8;
        float sum0 = 0.f, sum1 = 0.f;
#pragma unroll
        for (int j = 0; j < 8; ++j) {
            const int col = colBase + wn * 64 + j * 8 + t * 2;
            float e00 = __expf(acc[i][j][0]);
            float e01 = __expf(acc[i][j][1]);
            float e10 = __expf(acc[i][j][2]);
            float e11 = __expf(acc[i][j][3]);
            sum0 += e00 + e01;
            sum1 += e10 + e11;
            uint32_t h2, l2;
            split2(e00, e01, h2, l2);
            *(uint32_t*)(Hb + (long long)r0 * SEQ + col) = h2;
            *(uint32_t*)(Lb + (long long)r0 * SEQ + col) = l2;
            split2(e10, e11, h2, l2);
            *(uint32_t*)(Hb + (long long)r1 * SEQ + col) = h2;
            *(uint32_t*)(Lb + (long long)r1 * SEQ + col) = l2;
        }
        sum0 += __shfl_xor_sync(0xffffffffu, sum0, 1);
        sum0 += __shfl_xor_sync(0xffffffffu, sum0, 2);
        sum1 += __shfl_xor_sync(0xffffffffu, sum1, 1);
        sum1 += __shfl_xor_sync(0xffffffffu, sum1, 2);
        if (t == 0) {
            atomicAdd(rs + (long long)z * SEQ + r0, sum0);
            atomicAdd(rs + (long long)z * SEQ + r1, sum1);
        }
    }
}

// ---------------------------------------------------------------------------
// PV kernel: out = (E V) / rowsum
// ---------------------------------------------------------------------------
__global__ __launch_bounds__(256, 2)
void pv_mma(const __nv_bfloat16* __restrict__ Ph, const __nv_bfloat16* __restrict__ Pl,
            const __nv_bfloat16* __restrict__ Vth, const __nv_bfloat16* __restrict__ Vtl,
            const float* __restrict__ rs, float* __restrict__ out)
{
    extern __shared__ char smem[];
    const uint32_t sbase = smem_to_u32(smem);
    const int tid = threadIdx.x;
    const int wid = tid >> 5;
    const int lid = tid & 31;
    const int wm  = wid & 3;
    const int wn  = wid >> 2;
    const int rowBase = blockIdx.y * 128;
    const int colBase = blockIdx.x * 128;
    const int z = blockIdx.z;

    const __nv_bfloat16* Ahi_p = Ph + (long long)z * SEQ * SEQ;
    const __nv_bfloat16* Alo_p = Pl + (long long)z * SEQ * SEQ;
    const __nv_bfloat16* Bhi_p = Vth + (long long)z * DIM * SEQ;
    const __nv_bfloat16* Blo_p = Vtl + (long long)z * DIM * SEQ;

    float acc[2][8][4];
#pragma unroll
    for (int i = 0; i < 2; ++i)
#pragma unroll
        for (int j = 0; j < 8; ++j)
#pragma unroll
            for (int q = 0; q < 4; ++q) acc[i][j][q] = 0.0f;

    GEMM_MAINLOOP(Ahi_p, Alo_p, Bhi_p, Blo_p, SEQ)

    const int g = lid >> 2, t = lid & 3;
    float* C_b = out + (long long)z * SEQ * DIM;
#pragma unroll
    for (int i = 0; i < 2; ++i) {
        const int r0 = rowBase + wm * 32 + i * 16 + g;
        const int r1 = r0 + 8;
        const float inv0 = 1.0f / __ldg(rs + (long long)z * SEQ + r0);
        const float inv1 = 1.0f / __ldg(rs + (long long)z * SEQ + r1);
#pragma unroll
        for (int j = 0; j < 8; ++j) {
            const int col = colBase + wn * 64 + j * 8 + t * 2;
            *(float2*)(C_b + (long long)r0 * DIM + col) =
                make_float2(acc[i][j][0] * inv0, acc[i][j][1] * inv0);
            *(float2*)(C_b + (long long)r1 * DIM + col) =
                make_float2(acc[i][j][2] * inv1, acc[i][j][3] * inv1);
        }
    }
}

// ---------------------------------------------------------------------------
// Split fp32 -> (hi, lo) bf16 (x) + zero the rowsum buffer (fused)
// ---------------------------------------------------------------------------
__global__ __launch_bounds__(256)
void split_zero_kernel(const float4* __restrict__ in, uint2* __restrict__ hi,
                       uint2* __restrict__ lo, float* __restrict__ rs, long long n4)
{
    long long i = (long long)blockIdx.x * 256 + threadIdx.x;
    if (i < ROWS) rs[i] = 0.0f;
    if (i >= n4) return;
    float4 v = in[i];
    uint32_t h01, l01, h23, l23;
    split2(v.x, v.y, h01, l01);
    split2(v.z, v.w, h23, l23);
    uint2 ho, lo2;
    ho.x = h01; ho.y = h23;
    lo2.x = l01; lo2.y = l23;
    hi[i] = ho;
    lo[i] = lo2;
}

// Transpose fp32 [DIM,DIM] -> bf16 hi/lo, all three weights in one launch.
__global__ __launch_bounds__(256)
void transpose_split3_kernel(const float* __restrict__ Wq, const float* __restrict__ Wk,
                             const float* __restrict__ Wv,
                             __nv_bfloat16* __restrict__ Qh, __nv_bfloat16* __restrict__ Ql,
                             __nv_bfloat16* __restrict__ Kh, __nv_bfloat16* __restrict__ Kl,
                             __nv_bfloat16* __restrict__ Vh, __nv_bfloat16* __restrict__ Vl)
{
    __shared__ float t[32][33];
    const int z = blockIdx.z;
    const float* in = (z == 0) ? Wq : (z == 1) ? Wk : Wv;
    __nv_bfloat16* hi = (z == 0) ? Qh : (z == 1) ? Kh : Vh;
    __nv_bfloat16* lo = (z == 0) ? Ql : (z == 1) ? Kl : Vl;

    const int tx = threadIdx.x, ty = threadIdx.y;
    const int x = blockIdx.x * 32 + tx;
    const int y0 = blockIdx.y * 32;
#pragma unroll
    for (int j = 0; j < 4; ++j)
        t[ty + j * 8][tx] = in[(long long)(y0 + ty + j * 8) * DIM + x];
    __syncthreads();

    const int ox = blockIdx.y * 32 + tx;
    const int oy0 = blockIdx.x * 32;
#pragma unroll
    for (int j = 0; j < 4; ++j) {
        float v = t[tx][ty + j * 8];
        __nv_bfloat16 h = __float2bfloat16(v);
        __nv_bfloat16 l = __float2bfloat16(v - __bfloat162float(h));
        long long o = (long long)(oy0 + ty + j * 8) * DIM + ox;
        hi[o] = h;
        lo[o] = l;
    }
}

// ---------------------------------------------------------------------------
extern "C" void kernel_launch(void* const* d_in, const int* in_sizes, int n_in,
                              void* d_out, int out_size)
{
    const float* x  = (const float*)d_in[0];
    const float* Wq = (const float*)d_in[1];
    const float* bq = (const float*)d_in[2];
    const float* Wk = (const float*)d_in[3];
    const float* bk = (const float*)d_in[4];
    const float* Wv = (const float*)d_in[5];
    const float* bv = (const float*)d_in[6];
    float* out = (float*)d_out;

    __nv_bfloat16 *xhi, *xlo, *Wqthi, *Wqtlo, *Wkthi, *Wktlo, *Wvthi, *Wvtlo;
    __nv_bfloat16 *Qhi, *Qlo, *Khi, *Klo, *Vthi, *Vtlo, *Phi, *Plo;
    float *rs;
    cudaGetSymbolAddress((void**)&xhi, g_xhi);     cudaGetSymbolAddress((void**)&xlo, g_xlo);
    cudaGetSymbolAddress((void**)&Wqthi, g_Wqthi); cudaGetSymbolAddress((void**)&Wqtlo, g_Wqtlo);
    cudaGetSymbolAddress((void**)&Wkthi, g_Wkthi); cudaGetSymbolAddress((void**)&Wktlo, g_Wktlo);
    cudaGetSymbolAddress((void**)&Wvthi, g_Wvthi); cudaGetSymbolAddress((void**)&Wvtlo, g_Wvtlo);
    cudaGetSymbolAddress((void**)&Qhi, g_Qhi); cudaGetSymbolAddress((void**)&Qlo, g_Qlo);
    cudaGetSymbolAddress((void**)&Khi, g_Khi); cudaGetSymbolAddress((void**)&Klo, g_Klo);
    cudaGetSymbolAddress((void**)&Vthi, g_Vthi); cudaGetSymbolAddress((void**)&Vtlo, g_Vtlo);
    cudaGetSymbolAddress((void**)&Phi, g_Phi); cudaGetSymbolAddress((void**)&Plo, g_Plo);
    cudaGetSymbolAddress((void**)&rs, g_rowsum);

    cudaFuncSetAttribute(proj_mma,   cudaFuncAttributeMaxDynamicSharedMemorySize, GEMM_SMEM);
    cudaFuncSetAttribute(scores_mma, cudaFuncAttributeMaxDynamicSharedMemorySize, GEMM_SMEM);
    cudaFuncSetAttribute(pv_mma,     cudaFuncAttributeMaxDynamicSharedMemorySize, GEMM_SMEM);

    // 1) Split x (+ zero rowsums)
    {
        long long n4 = (long long)ROWS * DIM / 4;
        split_zero_kernel<<<(unsigned)((n4 + 255) / 256), 256>>>(
            (const float4*)x, (uint2*)xhi, (uint2*)xlo, rs, n4);
    }
    // 2) Transpose+split all three weights in one launch
    transpose_split3_kernel<<<dim3(DIM / 32, DIM / 32, 3), dim3(32, 8)>>>(
        Wq, Wk, Wv, Wqthi, Wqtlo, Wkthi, Wktlo, Wvthi, Wvtlo);

    // 3) All three projections in ONE launch (z: 0=Q, 1=K, 2=V)
    {
        dim3 g(DIM / 128, ROWS / 128, 3);
        proj_mma<<<g, 256, GEMM_SMEM>>>(xhi, xlo,
                                        Wqthi, Wqtlo, Wkthi, Wktlo, Wvthi, Wvtlo,
                                        bq, bk, bv,
                                        Qhi, Qlo, Khi, Klo, Vthi, Vtlo);
    }
    // 4) Scores with fused exp + split + rowsum
    {
        dim3 g(SEQ / 128, SEQ / 128, BATCH);
        scores_mma<<<g, 256, GEMM_SMEM>>>(Qhi, Qlo, Khi, Klo, Phi, Plo, rs);
    }
    // 5) Out: out[b] = (E[b] @ V[b]) / rowsum
    {
        dim3 g(DIM / 128, SEQ / 128, BATCH);
        pv_mma<<<g, 256, GEMM_SMEM>>>(Phi, Plo, Vthi, Vtlo, rs, out);
    }
}

// round 16
// speedup vs baseline: 1.0582x; 1.0288x over previous
#include <cuda_runtime.h>
#include <cuda_bf16.h>
#include <cstdint>

// Problem constants: B=8, N=2048, D=DQ=DV=1024
#define BATCH 8
#define SEQ   2048
#define DIM   1024
#define ROWS  (BATCH * SEQ)        // 16384

// ---------------------------------------------------------------------------
// Device scratch
// ---------------------------------------------------------------------------
__device__ __nv_bfloat16 g_xhi[(size_t)ROWS * DIM];
__device__ __nv_bfloat16 g_xlo[(size_t)ROWS * DIM];
__device__ __nv_bfloat16 g_Wqthi[(size_t)DIM * DIM], g_Wqtlo[(size_t)DIM * DIM];
__device__ __nv_bfloat16 g_Wkthi[(size_t)DIM * DIM], g_Wktlo[(size_t)DIM * DIM];
__device__ __nv_bfloat16 g_Wvthi[(size_t)DIM * DIM], g_Wvtlo[(size_t)DIM * DIM];
__device__ __nv_bfloat16 g_Qhi[(size_t)ROWS * DIM], g_Qlo[(size_t)ROWS * DIM];
__device__ __nv_bfloat16 g_Khi[(size_t)ROWS * DIM], g_Klo[(size_t)ROWS * DIM];
__device__ __nv_bfloat16 g_Vthi[(size_t)BATCH * DIM * SEQ], g_Vtlo[(size_t)BATCH * DIM * SEQ];
__device__ __nv_bfloat16 g_Phi[(size_t)BATCH * SEQ * SEQ], g_Plo[(size_t)BATCH * SEQ * SEQ];
__device__ float g_rowsum[(size_t)ROWS];

// ---------------------------------------------------------------------------
// PTX helpers (portable sm_80+: mma.sync / ldmatrix / cp.async / mbarrier)
// ---------------------------------------------------------------------------
__device__ __forceinline__ uint32_t smem_to_u32(const void* p) {
    uint32_t a;
    asm("{ .reg .u64 t; cvta.to.shared.u64 t, %1; cvt.u32.u64 %0, t; }" : "=r"(a) : "l"(p));
    return a;
}
__device__ __forceinline__ void cp16(uint32_t dst, const void* src) {
    asm volatile("cp.async.cg.shared.global [%0], [%1], 16;" :: "r"(dst), "l"(src));
}
__device__ __forceinline__ void mbar_init(uint32_t a, uint32_t cnt) {
    asm volatile("mbarrier.init.shared.b64 [%0], %1;" :: "r"(a), "r"(cnt) : "memory");
}
// NOINC variant: consumes the pre-initialized arrival count (the default
// variant increments expected-count first => net zero => deadlock, cf. R11).
__device__ __forceinline__ void cp_async_arrive_noinc(uint32_t a) {
    asm volatile("cp.async.mbarrier.arrive.noinc.shared.b64 [%0];" :: "r"(a) : "memory");
}
__device__ __forceinline__ void mbar_arrive(uint32_t a) {
    asm volatile("mbarrier.arrive.shared.b64 _, [%0];" :: "r"(a) : "memory");
}
#define MBARRIER_WAIT_PARITY(mbar_smem_addr, phase_parity) do { \
    uint32_t _mbar = (uint32_t)(mbar_smem_addr); \
    uint32_t _parity = (uint32_t)(phase_parity); \
    uint32_t _done; \
    asm volatile( \
        "{\n\t.reg .pred p;\n\t" \
        "mbarrier.try_wait.parity.acquire.cta.shared::cta.b64 p, [%1], %2;\n\t" \
        "selp.b32 %0, 1, 0, p;\n\t}" \
        : "=r"(_done) : "r"(_mbar), "r"(_parity) : "memory"); \
    if (!_done) { \
        asm volatile( \
            "{\n\t.reg .pred P1;\n\t" \
            "WAIT_LOOP_%=:\n\t" \
            "mbarrier.try_wait.parity.acquire.cta.shared::cta.b64 P1, [%0], %1, 0x989680;\n\t" \
            "@P1 bra.uni WAIT_DONE_%=;\n\t" \
            "bra.uni WAIT_LOOP_%=;\n\t" \
            "WAIT_DONE_%=:\n\t}" \
            :: "r"(_mbar), "r"(_parity) : "memory"); \
    } \
} while(0)

__device__ __forceinline__ void ldsm_x4(uint32_t* r, uint32_t addr) {
    asm volatile("ldmatrix.sync.aligned.m8n8.x4.shared.b16 {%0,%1,%2,%3}, [%4];"
        : "=r"(r[0]), "=r"(r[1]), "=r"(r[2]), "=r"(r[3]) : "r"(addr));
}
__device__ __forceinline__ void mma16816(float* d, const uint32_t* a, const uint32_t* b) {
    asm volatile("mma.sync.aligned.m16n8k16.row.col.f32.bf16.bf16.f32 "
        "{%0,%1,%2,%3}, {%4,%5,%6,%7}, {%8,%9}, {%0,%1,%2,%3};"
        : "+f"(d[0]), "+f"(d[1]), "+f"(d[2]), "+f"(d[3])
        : "r"(a[0]), "r"(a[1]), "r"(a[2]), "r"(a[3]), "r"(b[0]), "r"(b[1]));
}
__device__ __forceinline__ void split2(float a, float b, uint32_t& hi2, uint32_t& lo2) {
    __nv_bfloat16 ha = __float2bfloat16(a);
    __nv_bfloat16 hb = __float2bfloat16(b);
    __nv_bfloat16 la = __float2bfloat16(a - __bfloat162float(ha));
    __nv_bfloat16 lb = __float2bfloat16(b - __bfloat162float(hb));
    __nv_bfloat162 h; h.x = ha; h.y = hb;
    __nv_bfloat162 l; l.x = la; l.y = lb;
    hi2 = *(uint32_t*)&h;
    lo2 = *(uint32_t*)&l;
}

// ---------------------------------------------------------------------------
// Async-pipeline mainloop: 128x128 block tile, K-chunk 16, 4-stage mbarrier
// pipeline (no __syncthreads in the loop), 8 warps (4x2), warp 32x64, occ 2.
// Rows padded to 48 B: 16B-aligned cp.async dst AND conflict-free ldmatrix.
// Empty arrive moved EARLY: issued right after the last ldmatrix of the
// chunk (p==2 prefetch) — mbarrier.arrive release-orders the prior smem
// reads, so producers can start refilling while p==3 MMAs run on registers.
// ---------------------------------------------------------------------------
#define KC     16
#define SROW   48                        // bytes per smem row
#define TILEB  (128 * SROW)              // 6144 B
#define STAGEB (4 * TILEB)               // 24576 B (Ahi, Alo, Bhi, Blo)
#define NSTAGE 4
#define MB_OFF (NSTAGE * STAGEB)         // 98304
#define GEMM_SMEM (MB_OFF + 64)          // + mbarriers

#define GEMM_MAINLOOP(Ahi_p, Alo_p, Bhi_p, Blo_p, Kdim)                               \
    const uint32_t mbF = sbase + MB_OFF;        /* full[0..3]  */                      \
    const uint32_t mbE = sbase + MB_OFF + 32;   /* empty[0..3] */                      \
    if (tid == 0) {                                                                    \
        _Pragma("unroll")                                                              \
        for (int s = 0; s < NSTAGE; ++s) {                                             \
            mbar_init(mbF + s * 8, 256);                                               \
            mbar_init(mbE + s * 8, 256);                                               \
        }                                                                              \
    }                                                                                  \
    __syncthreads();                                                                   \
    const int ldrow = tid >> 1, ldhalf = tid & 1;                                      \
    auto load_chunk = [&](int c, int stage) {                                          \
        const uint32_t st = sbase + stage * STAGEB;                                    \
        const long long kOff = (long long)c * KC;                                      \
        const __nv_bfloat16* srcs[4] = { Ahi_p, Alo_p, Bhi_p, Blo_p };                 \
        _Pragma("unroll")                                                              \
        for (int t = 0; t < 4; ++t) {                                                  \
            const int rB = (t < 2) ? rowBase : colBase;                                \
            cp16(st + t * TILEB + ldrow * SROW + ldhalf * 16,                          \
                 srcs[t] + (long long)(rB + ldrow) * (Kdim) + kOff + ldhalf * 8);      \
        }                                                                              \
    };                                                                                 \
    const uint32_t aRowOff = (uint32_t)(lid & 15) * SROW + (uint32_t)(lid >> 4) * 16;  \
    const uint32_t bRowOff = ((uint32_t)(lid & 7) + ((uint32_t)(lid >> 4) & 1) * 8) * SROW \
                           + (((uint32_t)(lid >> 3) & 1)) * 16;                        \
    const int nChunks = (Kdim) / KC;                                                   \
    _Pragma("unroll")                                                                  \
    for (int pc = 0; pc < 3; ++pc) {                                                   \
        if (pc < nChunks) { load_chunk(pc, pc); cp_async_arrive_noinc(mbF + pc * 8); } \
    }                                                                                  \
    for (int c = 0; c < nChunks; ++c) {                                                \
        const int s = c & 3;                                                           \
        MBARRIER_WAIT_PARITY(mbF + s * 8, (uint32_t)((c >> 2) & 1));                   \
        const uint32_t st = sbase + s * STAGEB;                                        \
        const uint32_t aHiB = st + 0 * TILEB + (uint32_t)(wm * 32) * SROW + aRowOff;   \
        const uint32_t aLoB = st + 1 * TILEB + (uint32_t)(wm * 32) * SROW + aRowOff;   \
        const uint32_t bHiB = st + 2 * TILEB + (uint32_t)(wn * 64) * SROW + bRowOff;   \
        const uint32_t bLoB = st + 3 * TILEB + (uint32_t)(wn * 64) * SROW + bRowOff;   \
        uint32_t ah[2][4], al[2][4];                                                   \
        ldsm_x4(ah[0], aHiB);                                                          \
        ldsm_x4(ah[1], aHiB + 16 * SROW);                                              \
        ldsm_x4(al[0], aLoB);                                                          \
        ldsm_x4(al[1], aLoB + 16 * SROW);                                              \
        uint32_t rhc[4], rlc[4], rhn[4], rln[4];                                       \
        ldsm_x4(rhc, bHiB);                                                            \
        ldsm_x4(rlc, bLoB);                                                            \
        _Pragma("unroll")                                                              \
        for (int p = 0; p < 4; ++p) {                                                  \
            if (p < 3) {                                                               \
                ldsm_x4(rhn, bHiB + (uint32_t)((p + 1) * 16) * SROW);                  \
                ldsm_x4(rln, bLoB + (uint32_t)((p + 1) * 16) * SROW);                  \
            }                                                                          \
            if (p == 2) mbar_arrive(mbE + s * 8);  /* all stage-s reads issued */      \
            uint32_t bh0[2] = { rhc[0], rhc[1] }, bh1[2] = { rhc[2], rhc[3] };         \
            uint32_t bl0[2] = { rlc[0], rlc[1] }, bl1[2] = { rlc[2], rlc[3] };         \
            float* a00 = acc[0][p * 2];                                                \
            float* a10 = acc[1][p * 2];                                                \
            float* a01 = acc[0][p * 2 + 1];                                            \
            float* a11 = acc[1][p * 2 + 1];                                            \
            mma16816(a00, ah[0], bh0);                                                 \
            mma16816(a10, ah[1], bh0);                                                 \
            mma16816(a01, ah[0], bh1);                                                 \
            mma16816(a11, ah[1], bh1);                                                 \
            mma16816(a00, ah[0], bl0);                                                 \
            mma16816(a10, ah[1], bl0);                                                 \
            mma16816(a01, ah[0], bl1);                                                 \
            mma16816(a11, ah[1], bl1);                                                 \
            mma16816(a00, al[0], bh0);                                                 \
            mma16816(a10, al[1], bh0);                                                 \
            mma16816(a01, al[0], bh1);                                                 \
            mma16816(a11, al[1], bh1);                                                 \
            if (p < 3) {                                                               \
                rhc[0] = rhn[0]; rhc[1] = rhn[1]; rhc[2] = rhn[2]; rhc[3] = rhn[3];    \
                rlc[0] = rln[0]; rlc[1] = rln[1]; rlc[2] = rln[2]; rlc[3] = rln[3];    \
            }                                                                          \
        }                                                                              \
        if (c + 3 < nChunks) {                                                         \
            const int s3 = (c + 3) & 3;                                                \
            if (c >= 1) MBARRIER_WAIT_PARITY(mbE + s3 * 8,                             \
                                             (uint32_t)(((c - 1) >> 2) & 1));          \
            load_chunk(c + 3, s3);                                                     \
            cp_async_arrive_noinc(mbF + s3 * 8);                                       \
        }                                                                              \
    }

// ---------------------------------------------------------------------------
// Merged projection kernel: grid.z selects Q(0)/K(1)/V(2).
// ---------------------------------------------------------------------------
__global__ __launch_bounds__(256, 2)
void proj_mma(const __nv_bfloat16* __restrict__ xhi, const __nv_bfloat16* __restrict__ xlo,
              const __nv_bfloat16* __restrict__ Wqh, const __nv_bfloat16* __restrict__ Wql,
              const __nv_bfloat16* __restrict__ Wkh, const __nv_bfloat16* __restrict__ Wkl,
              const __nv_bfloat16* __restrict__ Wvh, const __nv_bfloat16* __restrict__ Wvl,
              const float* __restrict__ bq, const float* __restrict__ bk,
              const float* __restrict__ bv,
              __nv_bfloat16* __restrict__ Qh, __nv_bfloat16* __restrict__ Ql,
              __nv_bfloat16* __restrict__ Kh, __nv_bfloat16* __restrict__ Kl,
              __nv_bfloat16* __restrict__ Vth, __nv_bfloat16* __restrict__ Vtl)
{
    extern __shared__ char smem[];
    const uint32_t sbase = smem_to_u32(smem);
    const int tid = threadIdx.x;
    const int wid = tid >> 5;
    const int lid = tid & 31;
    const int wm  = wid & 3;
    const int wn  = wid >> 2;
    const int rowBase = blockIdx.y * 128;
    const int colBase = blockIdx.x * 128;
    const int z = blockIdx.z;          // 0=Q 1=K 2=V

    const __nv_bfloat16* Bh = (z == 0) ? Wqh : (z == 1) ? Wkh : Wvh;
    const __nv_bfloat16* Bl = (z == 0) ? Wql : (z == 1) ? Wkl : Wvl;
    const float* bias       = (z == 0) ? bq  : (z == 1) ? bk  : bv;

    float acc[2][8][4];
#pragma unroll
    for (int i = 0; i < 2; ++i)
#pragma unroll
        for (int j = 0; j < 8; ++j)
#pragma unroll
            for (int q = 0; q < 4; ++q) acc[i][j][q] = 0.0f;

    GEMM_MAINLOOP(xhi, xlo, Bh, Bl, DIM)

    const int g = lid >> 2, t = lid & 3;
    if (z < 2) {
        __nv_bfloat16* Chi = (z == 0) ? Qh : Kh;
        __nv_bfloat16* Clo = (z == 0) ? Ql : Kl;
#pragma unroll
        for (int i = 0; i < 2; ++i) {
            const int r0 = rowBase + wm * 32 + i * 16 + g;
            const int r1 = r0 + 8;
#pragma unroll
            for (int j = 0; j < 8; ++j) {
                const int col = colBase + wn * 64 + j * 8 + t * 2;
                float b0 = __ldg(bias + col), b1 = __ldg(bias + col + 1);
                uint32_t h2, l2;
                split2(acc[i][j][0] + b0, acc[i][j][1] + b1, h2, l2);
                *(uint32_t*)(Chi + (long long)r0 * DIM + col) = h2;
                *(uint32_t*)(Clo + (long long)r0 * DIM + col) = l2;
                split2(acc[i][j][2] + b0, acc[i][j][3] + b1, h2, l2);
                *(uint32_t*)(Chi + (long long)r1 * DIM + col) = h2;
                *(uint32_t*)(Clo + (long long)r1 * DIM + col) = l2;
            }
        }
    } else {
        // V: transposed split output Vt[DIM, SEQ] per batch, smem-staged
        __syncthreads();
        float* buf = (float*)smem;
#pragma unroll
        for (int i = 0; i < 2; ++i) {
            const int lr = wm * 32 + i * 16 + g;
#pragma unroll
            for (int j = 0; j < 8; ++j) {
                const int lc = wn * 64 + j * 8 + t * 2;
                float b0 = __ldg(bias + colBase + lc);
                float b1 = __ldg(bias + colBase + lc + 1);
                buf[lr * 129 + lc]           = acc[i][j][0] + b0;
                buf[lr * 129 + lc + 1]       = acc[i][j][1] + b1;
                buf[(lr + 8) * 129 + lc]     = acc[i][j][2] + b0;
                buf[(lr + 8) * 129 + lc + 1] = acc[i][j][3] + b1;
            }
        }
        __syncthreads();
        const int dcol = tid >> 1;
        const int sb2  = (tid & 1) * 64;
        const int bIdx = rowBase >> 11;
        const int srow0 = rowBase & (SEQ - 1);
        long long o = (long long)bIdx * DIM * SEQ + (long long)(colBase + dcol) * SEQ
                    + srow0 + sb2;
        __nv_bfloat16* Hb = Vth + o;
        __nv_bfloat16* Lb = Vtl + o;
#pragma unroll
        for (int s2 = 0; s2 < 64; s2 += 2) {
            float v0 = buf[(sb2 + s2) * 129 + dcol];
            float v1 = buf[(sb2 + s2 + 1) * 129 + dcol];
            uint32_t h2, l2;
            split2(v0, v1, h2, l2);
            *(uint32_t*)(Hb + s2) = h2;
            *(uint32_t*)(Lb + s2) = l2;
        }
    }
}

// ---------------------------------------------------------------------------
// Scores kernel: S = Q K^T, epilogue exp + split + atomic row sums.
// ---------------------------------------------------------------------------
__global__ __launch_bounds__(256, 2)
void scores_mma(const __nv_bfloat16* __restrict__ Qh, const __nv_bfloat16* __restrict__ Ql,
                const __nv_bfloat16* __restrict__ Kh, const __nv_bfloat16* __restrict__ Kl,
                __nv_bfloat16* __restrict__ Ph, __nv_bfloat16* __restrict__ Pl,
                float* __restrict__ rs)
{
    extern __shared__ char smem[];
    const uint32_t sbase = smem_to_u32(smem);
    const int tid = threadIdx.x;
    const int wid = tid >> 5;
    const int lid = tid & 31;
    const int wm  = wid & 3;
    const int wn  = wid >> 2;
    const int rowBase = blockIdx.y * 128;
    const int colBase = blockIdx.x * 128;
    const int z = blockIdx.z;

    const __nv_bfloat16* Ahi_p = Qh + (long long)z * SEQ * DIM;
    const __nv_bfloat16* Alo_p = Ql + (long long)z * SEQ * DIM;
    const __nv_bfloat16* Bhi_p = Kh + (long long)z * SEQ * DIM;
    const __nv_bfloat16* Blo_p = Kl + (long long)z * SEQ * DIM;

    float acc[2][8][4];
#pragma unroll
    for (int i = 0; i < 2; ++i)
#pragma unroll
        for (int j = 0; j < 8; ++j)
#pragma unroll
            for (int q = 0; q < 4; ++q) acc[i][j][q] = 0.0f;

    GEMM_MAINLOOP(Ahi_p, Alo_p, Bhi_p, Blo_p, DIM)

    const int g = lid >> 2, t = lid & 3;
    __nv_bfloat16* Hb = Ph + (long long)z * SEQ * SEQ;
    __nv_bfloat16* Lb = Pl + (long long)z * SEQ * SEQ;
#pragma unroll
    for (int i = 0; i < 2; ++i) {
        const int r0 = rowBase + wm * 32 + i * 16 + g;
        const int r1 = r0 + 8;
        float sum0 = 0.f, sum1 = 0.f;
#pragma unroll
        for (int j = 0; j < 8; ++j) {
            const int col = colBase + wn * 64 + j * 8 + t * 2;
            float e00 = __expf(acc[i][j][0]);
            float e01 = __expf(acc[i][j][1]);
            float e10 = __expf(acc[i][j][2]);
            float e11 = __expf(acc[i][j][3]);
            sum0 += e00 + e01;
            sum1 += e10 + e11;
            uint32_t h2, l2;
            split2(e00, e01, h2, l2);
            *(uint32_t*)(Hb + (long long)r0 * SEQ + col) = h2;
            *(uint32_t*)(Lb + (long long)r0 * SEQ + col) = l2;
            split2(e10, e11, h2, l2);
            *(uint32_t*)(Hb + (long long)r1 * SEQ + col) = h2;
            *(uint32_t*)(Lb + (long long)r1 * SEQ + col) = l2;
        }
        sum0 += __shfl_xor_sync(0xffffffffu, sum0, 1);
        sum0 += __shfl_xor_sync(0xffffffffu, sum0, 2);
        sum1 += __shfl_xor_sync(0xffffffffu, sum1, 1);
        sum1 += __shfl_xor_sync(0xffffffffu, sum1, 2);
        if (t == 0) {
            atomicAdd(rs + (long long)z * SEQ + r0, sum0);
            atomicAdd(rs + (long long)z * SEQ + r1, sum1);
        }
    }
}

// ---------------------------------------------------------------------------
// PV kernel: out = (E V) / rowsum
// ---------------------------------------------------------------------------
__global__ __launch_bounds__(256, 2)
void pv_mma(const __nv_bfloat16* __restrict__ Ph, const __nv_bfloat16* __restrict__ Pl,
            const __nv_bfloat16* __restrict__ Vth, const __nv_bfloat16* __restrict__ Vtl,
            const float* __restrict__ rs, float* __restrict__ out)
{
    extern __shared__ char smem[];
    const uint32_t sbase = smem_to_u32(smem);
    const int tid = threadIdx.x;
    const int wid = tid >> 5;
    const int lid = tid & 31;
    const int wm  = wid & 3;
    const int wn  = wid >> 2;
    const int rowBase = blockIdx.y * 128;
    const int colBase = blockIdx.x * 128;
    const int z = blockIdx.z;

    const __nv_bfloat16* Ahi_p = Ph + (long long)z * SEQ * SEQ;
    const __nv_bfloat16* Alo_p = Pl + (long long)z * SEQ * SEQ;
    const __nv_bfloat16* Bhi_p = Vth + (long long)z * DIM * SEQ;
    const __nv_bfloat16* Blo_p = Vtl + (long long)z * DIM * SEQ;

    float acc[2][8][4];
#pragma unroll
    for (int i = 0; i < 2; ++i)
#pragma unroll
        for (int j = 0; j < 8; ++j)
#pragma unroll
            for (int q = 0; q < 4; ++q) acc[i][j][q] = 0.0f;

    GEMM_MAINLOOP(Ahi_p, Alo_p, Bhi_p, Blo_p, SEQ)

    const int g = lid >> 2, t = lid & 3;
    float* C_b = out + (long long)z * SEQ * DIM;
#pragma unroll
    for (int i = 0; i < 2; ++i) {
        const int r0 = rowBase + wm * 32 + i * 16 + g;
        const int r1 = r0 + 8;
        const float inv0 = 1.0f / __ldg(rs + (long long)z * SEQ + r0);
        const float inv1 = 1.0f / __ldg(rs + (long long)z * SEQ + r1);
#pragma unroll
        for (int j = 0; j < 8; ++j) {
            const int col = colBase + wn * 64 + j * 8 + t * 2;
            *(float2*)(C_b + (long long)r0 * DIM + col) =
                make_float2(acc[i][j][0] * inv0, acc[i][j][1] * inv0);
            *(float2*)(C_b + (long long)r1 * DIM + col) =
                make_float2(acc[i][j][2] * inv1, acc[i][j][3] * inv1);
        }
    }
}

// ---------------------------------------------------------------------------
// Split fp32 -> (hi, lo) bf16 (x) + zero the rowsum buffer (fused)
// ---------------------------------------------------------------------------
__global__ __launch_bounds__(256)
void split_zero_kernel(const float4* __restrict__ in, uint2* __restrict__ hi,
                       uint2* __restrict__ lo, float* __restrict__ rs, long long n4)
{
    long long i = (long long)blockIdx.x * 256 + threadIdx.x;
    if (i < ROWS) rs[i] = 0.0f;
    if (i >= n4) return;
    float4 v = in[i];
    uint32_t h01, l01, h23, l23;
    split2(v.x, v.y, h01, l01);
    split2(v.z, v.w, h23, l23);
    uint2 ho, lo2;
    ho.x = h01; ho.y = h23;
    lo2.x = l01; lo2.y = l23;
    hi[i] = ho;
    lo[i] = lo2;
}

// Transpose fp32 [DIM,DIM] -> bf16 hi/lo, all three weights in one launch.
__global__ __launch_bounds__(256)
void transpose_split3_kernel(const float* __restrict__ Wq, const float* __restrict__ Wk,
                             const float* __restrict__ Wv,
                             __nv_bfloat16* __restrict__ Qh, __nv_bfloat16* __restrict__ Ql,
                             __nv_bfloat16* __restrict__ Kh, __nv_bfloat16* __restrict__ Kl,
                             __nv_bfloat16* __restrict__ Vh, __nv_bfloat16* __restrict__ Vl)
{
    __shared__ float t[32][33];
    const int z = blockIdx.z;
    const float* in = (z == 0) ? Wq : (z == 1) ? Wk : Wv;
    __nv_bfloat16* hi = (z == 0) ? Qh : (z == 1) ? Kh : Vh;
    __nv_bfloat16* lo = (z == 0) ? Ql : (z == 1) ? Kl : Vl;

    const int tx = threadIdx.x, ty = threadIdx.y;
    const int x = blockIdx.x * 32 + tx;
    const int y0 = blockIdx.y * 32;
#pragma unroll
    for (int j = 0; j < 4; ++j)
        t[ty + j * 8][tx] = in[(long long)(y0 + ty + j * 8) * DIM + x];
    __syncthreads();

    const int ox = blockIdx.y * 32 + tx;
    const int oy0 = blockIdx.x * 32;
#pragma unroll
    for (int j = 0; j < 4; ++j) {
        float v = t[tx][ty + j * 8];
        __nv_bfloat16 h = __float2bfloat16(v);
        __nv_bfloat16 l = __float2bfloat16(v - __bfloat162float(h));
        long long o = (long long)(oy0 + ty + j * 8) * DIM + ox;
        hi[o] = h;
        lo[o] = l;
    }
}

// ---------------------------------------------------------------------------
extern "C" void kernel_launch(void* const* d_in, const int* in_sizes, int n_in,
                              void* d_out, int out_size)
{
    const float* x  = (const float*)d_in[0];
    const float* Wq = (const float*)d_in[1];
    const float* bq = (const float*)d_in[2];
    const float* Wk = (const float*)d_in[3];
    const float* bk = (const float*)d_in[4];
    const float* Wv = (const float*)d_in[5];
    const float* bv = (const float*)d_in[6];
    float* out = (float*)d_out;

    __nv_bfloat16 *xhi, *xlo, *Wqthi, *Wqtlo, *Wkthi, *Wktlo, *Wvthi, *Wvtlo;
    __nv_bfloat16 *Qhi, *Qlo, *Khi, *Klo, *Vthi, *Vtlo, *Phi, *Plo;
    float *rs;
    cudaGetSymbolAddress((void**)&xhi, g_xhi);     cudaGetSymbolAddress((void**)&xlo, g_xlo);
    cudaGetSymbolAddress((void**)&Wqthi, g_Wqthi); cudaGetSymbolAddress((void**)&Wqtlo, g_Wqtlo);
    cudaGetSymbolAddress((void**)&Wkthi, g_Wkthi); cudaGetSymbolAddress((void**)&Wktlo, g_Wktlo);
    cudaGetSymbolAddress((void**)&Wvthi, g_Wvthi); cudaGetSymbolAddress((void**)&Wvtlo, g_Wvtlo);
    cudaGetSymbolAddress((void**)&Qhi, g_Qhi); cudaGetSymbolAddress((void**)&Qlo, g_Qlo);
    cudaGetSymbolAddress((void**)&Khi, g_Khi); cudaGetSymbolAddress((void**)&Klo, g_Klo);
    cudaGetSymbolAddress((void**)&Vthi, g_Vthi); cudaGetSymbolAddress((void**)&Vtlo, g_Vtlo);
    cudaGetSymbolAddress((void**)&Phi, g_Phi); cudaGetSymbolAddress((void**)&Plo, g_Plo);
    cudaGetSymbolAddress((void**)&rs, g_rowsum);

    cudaFuncSetAttribute(proj_mma,   cudaFuncAttributeMaxDynamicSharedMemorySize, GEMM_SMEM);
    cudaFuncSetAttribute(scores_mma, cudaFuncAttributeMaxDynamicSharedMemorySize, GEMM_SMEM);
    cudaFuncSetAttribute(pv_mma,     cudaFuncAttributeMaxDynamicSharedMemorySize, GEMM_SMEM);

    // 1) Split x (+ zero rowsums)
    {
        long long n4 = (long long)ROWS * DIM / 4;
        split_zero_kernel<<<(unsigned)((n4 + 255) / 256), 256>>>(
            (const float4*)x, (uint2*)xhi, (uint2*)xlo, rs, n4);
    }
    // 2) Transpose+split all three weights in one launch
    transpose_split3_kernel<<<dim3(DIM / 32, DIM / 32, 3), dim3(32, 8)>>>(
        Wq, Wk, Wv, Wqthi, Wqtlo, Wkthi, Wktlo, Wvthi, Wvtlo);

    // 3) All three projections in ONE launch (z: 0=Q, 1=K, 2=V)
    {
        dim3 g(DIM / 128, ROWS / 128, 3);
        proj_mma<<<g, 256, GEMM_SMEM>>>(xhi, xlo,
                                        Wqthi, Wqtlo, Wkthi, Wktlo, Wvthi, Wvtlo,
                                        bq, bk, bv,
                                        Qhi, Qlo, Khi, Klo, Vthi, Vtlo);
    }
    // 4) Scores with fused exp + split + rowsum
    {
        dim3 g(SEQ / 128, SEQ / 128, BATCH);
        scores_mma<<<g, 256, GEMM_SMEM>>>(Qhi, Qlo, Khi, Klo, Phi, Plo, rs);
    }
    // 5) Out: out[b] = (E[b] @ V[b]) / rowsum
    {
        dim3 g(DIM / 128, SEQ / 128, BATCH);
        pv_mma<<<g, 256, GEMM_SMEM>>>(Phi, Plo, Vthi, Vtlo, rs, out);
    }
}